// round 2
// baseline (speedup 1.0000x reference)
#include <cuda_runtime.h>
#include <cuda_bf16.h>

// Problem constants (from reference): B=8, H=64, Wd=128, D=272, NC=19, P=524288, NI=4096
#define D_FEAT 272
#define NC_OUT 19
#define BLOCK_THREADS 288   // 9 warps; threads [0,272) own one channel each
#define IDX_TILE 128

__global__ __launch_bounds__(BLOCK_THREADS)
void capsule_segmean_head_kernel(
    const float* __restrict__ feats,     // [B*H*Wd, D] flattened class_capsules
    const float* __restrict__ Wmat,      // [D, NC] row-major
    const float* __restrict__ bias,      // [NC]
    const int*   __restrict__ point_idx, // [P]
    const int*   __restrict__ seg_ids,   // [P], sorted ascending
    int P,
    float* __restrict__ out)             // [NI, NC]
{
    const int s   = blockIdx.x;
    const int tid = threadIdx.x;

    __shared__ int sh_range[2];
    __shared__ int sidx[IDX_TILE];
    __shared__ float pooled[D_FEAT];

    // Two threads each do one binary search (lower_bound of s and of s+1).
    if (tid < 2) {
        const int target = s + tid;   // tid==0 -> start, tid==1 -> end
        int lo = 0, hi = P;
        while (lo < hi) {
            int mid = (lo + hi) >> 1;
            if (__ldg(&seg_ids[mid]) < target) lo = mid + 1; else hi = mid;
        }
        sh_range[tid] = lo;
    }
    __syncthreads();
    const int start = sh_range[0];
    const int end   = sh_range[1];

    float acc = 0.0f;

    // Stage indices through shared in tiles so row loads are independent (high MLP).
    for (int base = start; base < end; base += IDX_TILE) {
        const int n = min(IDX_TILE, end - base);
        __syncthreads();
        if (tid < n) sidx[tid] = point_idx[base + tid];
        __syncthreads();

        if (tid < D_FEAT) {
            int i = 0;
            // 4-deep manual unroll: 4 independent LDGs in flight per thread.
            for (; i + 4 <= n; i += 4) {
                const int r0 = sidx[i + 0];
                const int r1 = sidx[i + 1];
                const int r2 = sidx[i + 2];
                const int r3 = sidx[i + 3];
                float v0 = __ldg(&feats[r0 * D_FEAT + tid]);
                float v1 = __ldg(&feats[r1 * D_FEAT + tid]);
                float v2 = __ldg(&feats[r2 * D_FEAT + tid]);
                float v3 = __ldg(&feats[r3 * D_FEAT + tid]);
                acc += v0 + v1 + v2 + v3;
            }
            for (; i < n; ++i) {
                acc += __ldg(&feats[sidx[i] * D_FEAT + tid]);
            }
        }
    }

    const float cnt = (float)max(end - start, 1);
    if (tid < D_FEAT) pooled[tid] = acc / cnt;
    __syncthreads();

    // Tiny head: 19 threads each compute one output column (dot over 272).
    if (tid < NC_OUT) {
        float o = __ldg(&bias[tid]);
        #pragma unroll 8
        for (int c = 0; c < D_FEAT; ++c) {
            o += pooled[c] * __ldg(&Wmat[c * NC_OUT + tid]);
        }
        out[s * NC_OUT + tid] = 1.0f / (1.0f + expf(-o));
    }
}

extern "C" void kernel_launch(void* const* d_in, const int* in_sizes, int n_in,
                              void* d_out, int out_size)
{
    // metadata order: class_capsules, W, b, point_idx, segment_ids, num_segments
    const float* feats     = (const float*)d_in[0];
    const float* Wmat      = (const float*)d_in[1];
    const float* bias      = (const float*)d_in[2];
    const int*   point_idx = (const int*)  d_in[3];
    const int*   seg_ids   = (const int*)  d_in[4];
    const int    P         = in_sizes[3];
    const int    NI        = out_size / NC_OUT;
    float* out = (float*)d_out;

    capsule_segmean_head_kernel<<<NI, BLOCK_THREADS>>>(
        feats, Wmat, bias, point_idx, seg_ids, P, out);
}

// round 4
// speedup vs baseline: 1.0251x; 1.0251x over previous
#include <cuda_runtime.h>
#include <cuda_bf16.h>

// B=8, H=64, Wd=128, D=272, NC=19, P=524288, NI=4096
#define D_FEAT   272
#define NQUAD    68          // 272 floats = 68 float4 per row (row stride 1088 B, 16B-aligned)
#define NLANE    4           // point-lanes processed concurrently
#define NC_OUT   19
#define BLOCK_THREADS 288    // 9 warps; threads [0,272) active: lane = t/68, quad = t%68
#define IDX_TILE 128

__global__ __launch_bounds__(BLOCK_THREADS)
void capsule_segmean_head_kernel(
    const float4* __restrict__ feats4,   // [B*H*Wd, 68] rows of float4
    const float*  __restrict__ Wmat,     // [D, NC] row-major
    const float*  __restrict__ bias,     // [NC]
    const int*    __restrict__ point_idx,// [P]
    const int*    __restrict__ seg_ids,  // [P], sorted ascending
    int P,
    float* __restrict__ out)             // [NI, NC]
{
    const int s   = blockIdx.x;
    const int tid = threadIdx.x;

    __shared__ int    sh_range[2];
    __shared__ int    sidx[IDX_TILE];
    __shared__ float4 red[NLANE][NQUAD];   // cross-lane reduction
    __shared__ float  pooled[D_FEAT];

    // lower_bound(s) and lower_bound(s+1) in parallel
    if (tid < 2) {
        const int target = s + tid;
        int lo = 0, hi = P;
        while (lo < hi) {
            int mid = (lo + hi) >> 1;
            if (__ldg(&seg_ids[mid]) < target) lo = mid + 1; else hi = mid;
        }
        sh_range[tid] = lo;
    }
    __syncthreads();
    const int start = sh_range[0];
    const int end   = sh_range[1];

    const int  lane   = tid / NQUAD;    // 0..3 (point-lane)
    const int  quad   = tid % NQUAD;    // 0..67 (channel quad)
    const bool active = tid < D_FEAT;   // 272 working threads

    float4 acc = make_float4(0.f, 0.f, 0.f, 0.f);

    for (int base = start; base < end; base += IDX_TILE) {
        const int n = min(IDX_TILE, end - base);
        __syncthreads();                       // protect sidx from previous iter readers
        if (tid < n) sidx[tid] = point_idx[base + tid];
        __syncthreads();

        if (active) {
            int i = lane;
            // 4-deep unroll: 4 independent float4 LDGs in flight per thread
            for (; i + 3 * NLANE < n; i += 4 * NLANE) {
                const int r0 = sidx[i];
                const int r1 = sidx[i +     NLANE];
                const int r2 = sidx[i + 2 * NLANE];
                const int r3 = sidx[i + 3 * NLANE];
                const float4 v0 = __ldg(&feats4[(long)r0 * NQUAD + quad]);
                const float4 v1 = __ldg(&feats4[(long)r1 * NQUAD + quad]);
                const float4 v2 = __ldg(&feats4[(long)r2 * NQUAD + quad]);
                const float4 v3 = __ldg(&feats4[(long)r3 * NQUAD + quad]);
                acc.x += v0.x + v1.x + v2.x + v3.x;
                acc.y += v0.y + v1.y + v2.y + v3.y;
                acc.z += v0.z + v1.z + v2.z + v3.z;
                acc.w += v0.w + v1.w + v2.w + v3.w;
            }
            for (; i < n; i += NLANE) {
                const float4 v = __ldg(&feats4[(long)sidx[i] * NQUAD + quad]);
                acc.x += v.x; acc.y += v.y; acc.z += v.z; acc.w += v.w;
            }
        }
    }

    if (active) red[lane][quad] = acc;
    __syncthreads();

    if (tid < NQUAD) {
        const float4 a = red[0][tid];
        const float4 b = red[1][tid];
        const float4 c = red[2][tid];
        const float4 d = red[3][tid];
        const float inv = 1.0f / (float)max(end - start, 1);
        pooled[tid * 4 + 0] = (a.x + b.x + c.x + d.x) * inv;
        pooled[tid * 4 + 1] = (a.y + b.y + c.y + d.y) * inv;
        pooled[tid * 4 + 2] = (a.z + b.z + c.z + d.z) * inv;
        pooled[tid * 4 + 3] = (a.w + b.w + c.w + d.w) * inv;
    }
    __syncthreads();

    // Head: 19 threads, one output column each (272-dot + sigmoid)
    if (tid < NC_OUT) {
        float o = __ldg(&bias[tid]);
        #pragma unroll 8
        for (int c = 0; c < D_FEAT; ++c) {
            o += pooled[c] * __ldg(&Wmat[c * NC_OUT + tid]);
        }
        out[s * NC_OUT + tid] = 1.0f / (1.0f + expf(-o));
    }
}

extern "C" void kernel_launch(void* const* d_in, const int* in_sizes, int n_in,
                              void* d_out, int out_size)
{
    const float4* feats4    = (const float4*)d_in[0];
    const float*  Wmat      = (const float*) d_in[1];
    const float*  bias      = (const float*) d_in[2];
    const int*    point_idx = (const int*)   d_in[3];
    const int*    seg_ids   = (const int*)   d_in[4];
    const int     P         = in_sizes[3];
    const int     NI        = out_size / NC_OUT;
    float* out = (float*)d_out;

    capsule_segmean_head_kernel<<<NI, BLOCK_THREADS>>>(
        feats4, Wmat, bias, point_idx, seg_ids, P, out);
}

// round 5
// speedup vs baseline: 1.5484x; 1.5105x over previous
#include <cuda_runtime.h>
#include <cuda_bf16.h>

// Problem constants: B=8,H=64,Wd=128 -> NROWS=65536, D=272, NC=19, P=524288, NI=4096
#define D_FEAT    272
#define NC_OUT    19
#define NC_PAD    20          // padded outputs (10 f32x2 pairs)
#define NROWS_MAX 65536
#define NI_MAX    4096

// ---- scratch (static __device__ allocations are allowed) ----
__device__ __align__(16) float g_proj[NROWS_MAX * NC_PAD];   // 5.24 MB
__device__ int g_off[NI_MAX + 1];

// ---- packed f32x2 helpers ----
__device__ __forceinline__ void ffma2(unsigned long long& d,
                                      unsigned long long a,
                                      unsigned long long b) {
    asm("fma.rn.f32x2 %0, %1, %2, %0;" : "+l"(d) : "l"(a), "l"(b));
}
__device__ __forceinline__ unsigned long long packdup(float x) {
    unsigned long long r;
    asm("mov.b64 %0, {%1, %1};" : "=l"(r) : "f"(x));
    return r;
}

// ============================================================
// Kernel 0: segment boundary scatter (seg_ids sorted ascending)
// g_off[s] = lower_bound(seg_ids, s); g_off[NI] = P
// ============================================================
__global__ void seg_offsets_kernel(const int* __restrict__ seg, int P, int NI)
{
    int i = blockIdx.x * blockDim.x + threadIdx.x;
    if (i >= P) return;
    int cur  = seg[i];
    int prev = (i == 0) ? -1 : seg[i - 1];
    for (int s = prev + 1; s <= cur; ++s) g_off[s] = i;
    if (i == P - 1) {
        for (int s = cur + 1; s <= NI; ++s) g_off[s] = P;
    }
}

// ============================================================
// Kernel 1: projection GEMM  proj[r][o] = sum_c feats[r][c] * W[c][o]
// Block: 128 threads, 256 rows/block (2 rows/thread), c-chunks of 16
// staged through padded smem; inner product uses fma.rn.f32x2 on
// output pairs (W pair broadcast from smem, x duplicated per lane).
// ============================================================
#define P1_THREADS 128
#define P1_ROWS    256
#define XS_STRIDE  17          // 16 floats + 1 pad -> conflict-free LDS

__global__ __launch_bounds__(P1_THREADS)
void proj_gemm_kernel(const float4* __restrict__ feats4,   // [NROWS, 68]
                      const float*  __restrict__ Wmat,     // [272, 19]
                      int nrows)
{
    __shared__ float wsh[D_FEAT * NC_PAD];     // 21.8 KB (col 19 zeroed)
    __shared__ float xs[P1_ROWS * XS_STRIDE];  // 17.4 KB

    const int tid = threadIdx.x;
    const int rowBase = blockIdx.x * P1_ROWS;

    // stage W (pad col 19 with zeros)
    for (int i = tid; i < D_FEAT * NC_PAD; i += P1_THREADS) {
        const int c = i / NC_PAD, o = i % NC_PAD;
        wsh[i] = (o < NC_OUT) ? Wmat[c * NC_OUT + o] : 0.0f;
    }

    const int r0 = rowBase + tid;
    const int r1 = rowBase + tid + P1_THREADS;
    const bool v0 = r0 < nrows, v1 = r1 < nrows;

    unsigned long long acc0[NC_PAD / 2], acc1[NC_PAD / 2];
    #pragma unroll
    for (int j = 0; j < NC_PAD / 2; ++j) { acc0[j] = 0ull; acc1[j] = 0ull; }

    for (int cc = 0; cc < D_FEAT; cc += 16) {
        __syncthreads();
        // stage 256 rows x 16 floats, coalesced-ish float4 global reads
        for (int j = tid; j < P1_ROWS * 4; j += P1_THREADS) {
            const int rr = j >> 2;
            const int qq = j & 3;
            const int gr = rowBase + rr;
            float4 val = make_float4(0.f, 0.f, 0.f, 0.f);
            if (gr < nrows) val = __ldg(&feats4[(long)gr * 68 + (cc >> 2) + qq]);
            float* dst = &xs[rr * XS_STRIDE + qq * 4];
            dst[0] = val.x; dst[1] = val.y; dst[2] = val.z; dst[3] = val.w;
        }
        __syncthreads();

        #pragma unroll
        for (int k = 0; k < 16; ++k) {
            const int c = cc + k;
            const unsigned long long x0p = packdup(xs[tid * XS_STRIDE + k]);
            const unsigned long long x1p = packdup(xs[(tid + P1_THREADS) * XS_STRIDE + k]);
            const unsigned long long* wrow =
                reinterpret_cast<const unsigned long long*>(&wsh[c * NC_PAD]);
            #pragma unroll
            for (int j = 0; j < NC_PAD / 2; ++j) {
                const unsigned long long w = wrow[j];   // LDS.64 broadcast
                ffma2(acc0[j], x0p, w);
                ffma2(acc1[j], x1p, w);
            }
        }
    }

    unsigned long long* proj8 = reinterpret_cast<unsigned long long*>(g_proj);
    if (v0) {
        #pragma unroll
        for (int j = 0; j < NC_PAD / 2; ++j)
            proj8[(long)r0 * (NC_PAD / 2) + j] = acc0[j];
    }
    if (v1) {
        #pragma unroll
        for (int j = 0; j < NC_PAD / 2; ++j)
            proj8[(long)r1 * (NC_PAD / 2) + j] = acc1[j];
    }
}

// ============================================================
// Kernel 2: gather projected rows, segment-mean, +bias, sigmoid
// one block (128 threads) per segment
// ============================================================
#define P2_THREADS 128

__global__ __launch_bounds__(P2_THREADS)
void pool_head_kernel(const int* __restrict__ point_idx,
                      const float* __restrict__ bias,
                      float* __restrict__ out)     // [NI, 19]
{
    const int s   = blockIdx.x;
    const int tid = threadIdx.x;
    const int start = g_off[s];
    const int end   = g_off[s + 1];

    const float4* proj4 = reinterpret_cast<const float4*>(g_proj);

    float4 a0 = make_float4(0.f,0.f,0.f,0.f);
    float4 a1 = a0, a2 = a0, a3 = a0, a4 = a0;

    for (int i = start + tid; i < end; i += P2_THREADS) {
        const long r = point_idx[i];
        const float4* row = proj4 + r * 5;
        const float4 v0 = __ldg(row + 0);
        const float4 v1 = __ldg(row + 1);
        const float4 v2 = __ldg(row + 2);
        const float4 v3 = __ldg(row + 3);
        const float4 v4 = __ldg(row + 4);
        a0.x += v0.x; a0.y += v0.y; a0.z += v0.z; a0.w += v0.w;
        a1.x += v1.x; a1.y += v1.y; a1.z += v1.z; a1.w += v1.w;
        a2.x += v2.x; a2.y += v2.y; a2.z += v2.z; a2.w += v2.w;
        a3.x += v3.x; a3.y += v3.y; a3.z += v3.z; a3.w += v3.w;
        a4.x += v4.x; a4.y += v4.y; a4.z += v4.z; a4.w += v4.w;
    }

    // warp butterfly reduce on 20 floats
    float vals[20] = { a0.x,a0.y,a0.z,a0.w, a1.x,a1.y,a1.z,a1.w,
                       a2.x,a2.y,a2.z,a2.w, a3.x,a3.y,a3.z,a3.w,
                       a4.x,a4.y,a4.z,a4.w };
    #pragma unroll
    for (int d = 16; d; d >>= 1) {
        #pragma unroll
        for (int j = 0; j < 20; ++j)
            vals[j] += __shfl_xor_sync(0xFFFFFFFFu, vals[j], d);
    }

    __shared__ float red[P2_THREADS / 32][20];
    const int warp = tid >> 5, lane = tid & 31;
    if (lane == 0) {
        #pragma unroll
        for (int j = 0; j < 20; ++j) red[warp][j] = vals[j];
    }
    __syncthreads();

    if (tid < NC_OUT) {
        float v = red[0][tid] + red[1][tid] + red[2][tid] + red[3][tid];
        const float inv = 1.0f / (float)max(end - start, 1);
        const float o = v * inv + __ldg(&bias[tid]);
        out[s * NC_OUT + tid] = 1.0f / (1.0f + expf(-o));
    }
}

// ============================================================
extern "C" void kernel_launch(void* const* d_in, const int* in_sizes, int n_in,
                              void* d_out, int out_size)
{
    // order: class_capsules, W, b, point_idx, segment_ids, num_segments
    const float4* feats4    = (const float4*)d_in[0];
    const float*  Wmat      = (const float*) d_in[1];
    const float*  bias      = (const float*) d_in[2];
    const int*    point_idx = (const int*)   d_in[3];
    const int*    seg_ids   = (const int*)   d_in[4];
    const int     P         = in_sizes[3];
    const int     nrows     = in_sizes[0] / D_FEAT;
    const int     NI        = out_size / NC_OUT;
    float* out = (float*)d_out;

    seg_offsets_kernel<<<(P + 255) / 256, 256>>>(seg_ids, P, NI);

    proj_gemm_kernel<<<(nrows + P1_ROWS - 1) / P1_ROWS, P1_THREADS>>>(
        feats4, Wmat, nrows);

    pool_head_kernel<<<NI, P2_THREADS>>>(point_idx, bias, out);
}